// round 8
// baseline (speedup 1.0000x reference)
#include <cuda_runtime.h>
#include <cuda_fp16.h>
#include <math.h>

#define H      1024
#define T      4096
#define NTHR   448          // 14 warps
#define NBLK   148
#define NBL    74           // blocks per layer
#define MAXU   14           // max units (h-indices) per block
#define RING   16
#define SMEM_W (MAXU * 8 * 128 * 16)   // 229376 B

__device__ float    g_h0[2][H];
__device__ float    g_h1[2][H];
__device__ unsigned g_count;
__device__ unsigned g_gen;
__device__ unsigned g_ring[RING][4][32];   // [slot][shard][128B pad]

__device__ __forceinline__ float sigmoidf_(float x) {
    return 1.0f / (1.0f + __expf(-x));
}

// gen-based grid barrier (used twice: after init, before cleanup)
__device__ __forceinline__ void gen_sync() {
    __syncthreads();
    if (threadIdx.x == 0) {
        volatile unsigned* vgen = &g_gen;
        unsigned gen = *vgen;
        __threadfence();
        if (atomicAdd(&g_count, 1u) == NBLK - 1u) {
            g_count = 0u;
            __threadfence();
            *vgen = gen + 1u;
        } else {
            while (*vgen == gen) { }
        }
        __threadfence();
    }
    __syncthreads();
}

__global__ __launch_bounds__(NTHR, 1)
void lstm_persistent(const int* __restrict__ idx,
                     const float* __restrict__ emb,
                     const float* __restrict__ W_ih,
                     const float* __restrict__ W_hh,
                     const float* __restrict__ b_ih,
                     const float* __restrict__ b_hh,
                     float* __restrict__ out) {
    extern __shared__ __align__(16) uint4 s_w[];   // [unit*8 + gate*2 + mat][128] uint4 (fp16)

    const int tid  = threadIdx.x;
    const int warp = tid >> 5;
    const int lane = tid & 31;
    const int blk  = blockIdx.x;
    const int layer = blk >= NBL ? 1 : 0;
    const int lb    = layer ? blk - NBL : blk;
    const int base  = (1024 * lb) / NBL;
    const int cnt   = (1024 * (lb + 1)) / NBL - base;   // 13 or 14
    const int j     = base + warp;
    const bool hasU = warp < cnt;

    // ---- fill smem weights (fp32 global -> fp16 smem), layout matches reads ----
    {
        const float* Wi = W_ih + (size_t)layer * 4096 * 1024;
        const float* Wh = W_hh + (size_t)layer * 4096 * 1024;
        const int total = cnt * 8 * 128;          // uint4 chunks
        for (int e = tid; e < total; e += NTHR) {
            const int k  = e & 127;
            const int rm = e >> 7;                // u*8 + g*2 + m
            const int m  = rm & 1;
            const int g  = (rm >> 1) & 3;
            const int u  = rm >> 3;
            const float* row = (m ? Wh : Wi)
                             + ((size_t)(g * 1024 + base + u)) * 1024 + k * 8;
            float4 a = *(const float4*)(row);
            float4 b = *(const float4*)(row + 4);
            uint4 o;
            *(__half2*)&o.x = __floats2half2_rn(a.x, a.y);
            *(__half2*)&o.y = __floats2half2_rn(a.z, a.w);
            *(__half2*)&o.z = __floats2half2_rn(b.x, b.y);
            *(__half2*)&o.w = __floats2half2_rn(b.z, b.w);
            s_w[e] = o;
        }
    }

    float bias[4];
    if (hasU) {
#pragma unroll
        for (int g = 0; g < 4; ++g)
            bias[g] = b_ih[layer * 4096 + g * 1024 + j]
                    + b_hh[layer * 4096 + g * 1024 + j];
    }
    float c = 0.0f;

    if (blk == 0) {
        for (int i = tid; i < H; i += NTHR) {
            g_h0[0][i] = 0.0f; g_h0[1][i] = 0.0f;
            g_h1[0][i] = 0.0f; g_h1[1][i] = 0.0f;
        }
    }
    __syncthreads();
    gen_sync();   // weights in smem + h zeroed, ring slots zero (static/prev cleanup)

    const size_t OUTS = (size_t)T * H;
    const size_t HT   = OUTS;
    const size_t CT   = OUTS + 2 * H;

    for (int p = 0; p <= T; ++p) {
        const bool active = hasU && (layer ? (p >= 1) : (p < T));
        if (active) {
            const int t = layer ? (p - 1) : p;
            const float* vi_g = layer ? &g_h0[(p - 1) & 1][0]
                                      : emb + (size_t)__ldg(&idx[p]) * H;
            const float* vh_g = layer ? &g_h1[p & 1][0]
                                      : &g_h0[(p - 1) & 1][0];

            // preload this lane's vector slices into registers (reused x4 gates)
            float4 VI[8], VH[8];
#pragma unroll
            for (int it = 0; it < 4; ++it) {
                const int k = lane + it * 32;
                VI[2 * it + 0] = __ldcg((const float4*)vi_g + 2 * k + 0);
                VI[2 * it + 1] = __ldcg((const float4*)vi_g + 2 * k + 1);
                VH[2 * it + 0] = __ldcg((const float4*)vh_g + 2 * k + 0);
                VH[2 * it + 1] = __ldcg((const float4*)vh_g + 2 * k + 1);
            }

            float acc[4];
#pragma unroll
            for (int g = 0; g < 4; ++g) {
                const uint4* wi_p = s_w + (warp * 8 + g * 2 + 0) * 128;
                const uint4* wh_p = s_w + (warp * 8 + g * 2 + 1) * 128;
                float a = 0.0f;
#pragma unroll
                for (int it = 0; it < 4; ++it) {
                    const int k = lane + it * 32;
                    uint4 wi = wi_p[k];
                    uint4 wh = wh_p[k];
                    float4 v0 = VI[2 * it + 0], v1 = VI[2 * it + 1];
                    float4 u0 = VH[2 * it + 0], u1 = VH[2 * it + 1];

                    float2 w0 = __half22float2(*(__half2*)&wi.x);
                    float2 w1 = __half22float2(*(__half2*)&wi.y);
                    float2 w2 = __half22float2(*(__half2*)&wi.z);
                    float2 w3 = __half22float2(*(__half2*)&wi.w);
                    a = fmaf(w0.x, v0.x, a); a = fmaf(w0.y, v0.y, a);
                    a = fmaf(w1.x, v0.z, a); a = fmaf(w1.y, v0.w, a);
                    a = fmaf(w2.x, v1.x, a); a = fmaf(w2.y, v1.y, a);
                    a = fmaf(w3.x, v1.z, a); a = fmaf(w3.y, v1.w, a);

                    float2 x0 = __half22float2(*(__half2*)&wh.x);
                    float2 x1 = __half22float2(*(__half2*)&wh.y);
                    float2 x2 = __half22float2(*(__half2*)&wh.z);
                    float2 x3 = __half22float2(*(__half2*)&wh.w);
                    a = fmaf(x0.x, u0.x, a); a = fmaf(x0.y, u0.y, a);
                    a = fmaf(x1.x, u0.z, a); a = fmaf(x1.y, u0.w, a);
                    a = fmaf(x2.x, u1.x, a); a = fmaf(x2.y, u1.y, a);
                    a = fmaf(x3.x, u1.z, a); a = fmaf(x3.y, u1.w, a);
                }
                acc[g] = a;
            }
#pragma unroll
            for (int off = 16; off > 0; off >>= 1) {
#pragma unroll
                for (int g = 0; g < 4; ++g)
                    acc[g] += __shfl_xor_sync(0xFFFFFFFFu, acc[g], off);
            }

            const float ig = sigmoidf_(acc[0] + bias[0]);
            const float fg = sigmoidf_(acc[1] + bias[1]);
            const float gg = tanhf(acc[2] + bias[2]);
            const float og = sigmoidf_(acc[3] + bias[3]);
            c = fg * c + ig * gg;
            const float h = og * tanhf(c);

            if (lane == 0) {
                if (layer) {
                    g_h1[(p - 1) & 1][j] = h;
                    out[(size_t)t * H + j] = h;
                    if (t == T - 1) { out[HT + H + j] = h; out[CT + H + j] = c; }
                } else {
                    g_h0[p & 1][j] = h;
                    if (p == T - 1) { out[HT + j] = h; out[CT + j] = c; }
                }
            }
        }

        // prefetch next embedding row into L2 (layer-0 blocks, warp 0)
        if (!layer && warp == 0 && p + 1 < T) {
            const char* row = (const char*)(emb + (size_t)__ldg(&idx[p + 1]) * H);
            asm volatile("prefetch.global.L2 [%0];" :: "l"(row + lane * 128));
        }

        // ---- sharded ring barrier ----
        __syncthreads();                      // all warps' h-stores issued
        if (tid == 0) {
            const int slot = p & (RING - 1);
            __threadfence();
            atomicAdd(&g_ring[slot][blk & 3][0], 1u);
            volatile unsigned* r0 = &g_ring[slot][0][0];
            volatile unsigned* r1 = &g_ring[slot][1][0];
            volatile unsigned* r2 = &g_ring[slot][2][0];
            volatile unsigned* r3 = &g_ring[slot][3][0];
            while (r0[0] + r1[0] + r2[0] + r3[0] < (unsigned)NBLK) { }
            __threadfence();
        }
        __syncthreads();

        // reset-ahead (slot p+8 was used at phase p-8; all blocks are past it)
        if (blk == 0 && tid == 0) {
            const int rs = (p + 8) & (RING - 1);
            g_ring[rs][0][0] = 0; g_ring[rs][1][0] = 0;
            g_ring[rs][2][0] = 0; g_ring[rs][3][0] = 0;
        }
    }

    // cleanup for graph replay: zero the whole ring after everyone is done
    gen_sync();
    if (blk == 0 && tid == 0) {
#pragma unroll
        for (int s = 0; s < RING; ++s) {
            g_ring[s][0][0] = 0; g_ring[s][1][0] = 0;
            g_ring[s][2][0] = 0; g_ring[s][3][0] = 0;
        }
    }
}

extern "C" void kernel_launch(void* const* d_in, const int* in_sizes, int n_in,
                              void* d_out, int out_size) {
    const int*   idx  = (const int*)d_in[0];
    const float* emb  = (const float*)d_in[1];
    const float* W_ih = (const float*)d_in[2];
    const float* W_hh = (const float*)d_in[3];
    const float* b_ih = (const float*)d_in[4];
    const float* b_hh = (const float*)d_in[5];
    float* out = (float*)d_out;

    static int attr_set = 0;
    if (!attr_set) {
        cudaFuncSetAttribute(lstm_persistent,
                             cudaFuncAttributeMaxDynamicSharedMemorySize, SMEM_W);
        attr_set = 1;
    }
    lstm_persistent<<<NBLK, NTHR, SMEM_W>>>(idx, emb, W_ih, W_hh, b_ih, b_hh, out);
    (void)in_sizes; (void)n_in; (void)out_size;
}

// round 11
// speedup vs baseline: 1.0788x; 1.0788x over previous
#include <cuda_runtime.h>
#include <cuda_fp16.h>
#include <math.h>

#define H      1024
#define T      4096
#define NTHR   448          // 14 warps
#define NBLK   148
#define NBL    74           // blocks per layer
#define MAXU   14
#define SMEM_W (MAXU * 8 * 128 * 16)   // 229376 B

__device__ float    g_h0[2][H];
__device__ float    g_h1[2][H];
__device__ unsigned g_count;
__device__ unsigned g_gen;

__device__ __forceinline__ float sigmoidf_(float x) {
    return 1.0f / (1.0f + __expf(-x));
}

__device__ __forceinline__ void stcg_f(float* p, float v) {
    asm volatile("st.global.cg.f32 [%0], %1;" :: "l"(p), "f"(v));
}

// gen-counter grid barrier — proven over 4097 iterations in R6 (128 blk) and
// R7 (148 blk). tid0 spins on ONE volatile word; all other warps parked at BAR.
__device__ __forceinline__ void grid_sync() {
    __syncthreads();
    if (threadIdx.x == 0) {
        volatile unsigned* vgen = &g_gen;
        unsigned gen = *vgen;
        __threadfence();
        if (atomicAdd(&g_count, 1u) == NBLK - 1u) {
            g_count = 0u;
            __threadfence();
            *vgen = gen + 1u;
        } else {
            while (*vgen == gen) { }
        }
        __threadfence();
    }
    __syncthreads();
}

__global__ __launch_bounds__(NTHR, 1)
void lstm_persistent(const int* __restrict__ idx,
                     const float* __restrict__ emb,
                     const float* __restrict__ W_ih,
                     const float* __restrict__ W_hh,
                     const float* __restrict__ b_ih,
                     const float* __restrict__ b_hh,
                     float* __restrict__ out) {
    extern __shared__ __align__(16) uint4 s_w[];   // [unit*8 + gate*2 + mat][128] uint4 fp16

    const int tid  = threadIdx.x;
    const int warp = tid >> 5;
    const int lane = tid & 31;
    const int blk  = blockIdx.x;
    const int layer = blk >= NBL ? 1 : 0;
    const int lb    = layer ? blk - NBL : blk;
    const int base  = (1024 * lb) / NBL;
    const int cnt   = (1024 * (lb + 1)) / NBL - base;   // 13 or 14
    const int j     = base + warp;
    const bool hasU = warp < cnt;

    // ---- fill smem weights (fp32 global -> fp16 smem) ----
    {
        const float* Wi = W_ih + (size_t)layer * 4096 * 1024;
        const float* Wh = W_hh + (size_t)layer * 4096 * 1024;
        const int total = cnt * 8 * 128;
        for (int e = tid; e < total; e += NTHR) {
            const int k  = e & 127;
            const int rm = e >> 7;
            const int m  = rm & 1;
            const int g  = (rm >> 1) & 3;
            const int u  = rm >> 3;
            const float* row = (m ? Wh : Wi)
                             + ((size_t)(g * 1024 + base + u)) * 1024 + k * 8;
            float4 a = *(const float4*)(row);
            float4 b = *(const float4*)(row + 4);
            uint4 o;
            *(__half2*)&o.x = __floats2half2_rn(a.x, a.y);
            *(__half2*)&o.y = __floats2half2_rn(a.z, a.w);
            *(__half2*)&o.z = __floats2half2_rn(b.x, b.y);
            *(__half2*)&o.w = __floats2half2_rn(b.z, b.w);
            s_w[e] = o;
        }
    }

    float bias[4];
    if (hasU) {
#pragma unroll
        for (int g = 0; g < 4; ++g)
            bias[g] = b_ih[layer * 4096 + g * 1024 + j]
                    + b_hh[layer * 4096 + g * 1024 + j];
    }
    float c = 0.0f;

    if (blk == 0) {
        for (int i = tid; i < H; i += NTHR) {
            g_h0[0][i] = 0.0f; g_h0[1][i] = 0.0f;
            g_h1[0][i] = 0.0f; g_h1[1][i] = 0.0f;
        }
    }
    grid_sync();

    const size_t OUTS = (size_t)T * H;
    const size_t HT   = OUTS;
    const size_t CT   = OUTS + 2 * H;

    // Wavefront: phase p -> L0 computes step p (p<T), L1 computes step p-1 (p>=1).
    for (int p = 0; p <= T; ++p) {
        const bool active = hasU && (layer ? (p >= 1) : (p < T));
        if (active) {
            const int t = layer ? (p - 1) : p;

            // ---- load input/recurrent vectors into registers ----
            float4 VI[8], VH[8];
            if (!layer) {
                const float4* e4 = (const float4*)(emb + (size_t)__ldg(&idx[p]) * H);
                const float4* h4 = (const float4*)&g_h0[(p - 1) & 1][0];
#pragma unroll
                for (int it = 0; it < 4; ++it) {
                    const int k = lane + it * 32;
                    VI[2 * it + 0] = __ldg(e4 + 2 * k + 0);
                    VI[2 * it + 1] = __ldg(e4 + 2 * k + 1);
                    VH[2 * it + 0] = __ldcg(h4 + 2 * k + 0);
                    VH[2 * it + 1] = __ldcg(h4 + 2 * k + 1);
                }
            } else {
                const float4* i4 = (const float4*)&g_h0[(p - 1) & 1][0];
                const float4* h4 = (const float4*)&g_h1[p & 1][0];   // h1[p-2]
#pragma unroll
                for (int it = 0; it < 4; ++it) {
                    const int k = lane + it * 32;
                    VI[2 * it + 0] = __ldcg(i4 + 2 * k + 0);
                    VI[2 * it + 1] = __ldcg(i4 + 2 * k + 1);
                    VH[2 * it + 0] = __ldcg(h4 + 2 * k + 0);
                    VH[2 * it + 1] = __ldcg(h4 + 2 * k + 1);
                }
            }

            // ---- 4 gate dot products from SMEM weights ----
            float acc[4];
#pragma unroll
            for (int g = 0; g < 4; ++g) {
                const uint4* wi_p = s_w + (warp * 8 + g * 2 + 0) * 128;
                const uint4* wh_p = s_w + (warp * 8 + g * 2 + 1) * 128;
                float a = 0.0f;
#pragma unroll
                for (int it = 0; it < 4; ++it) {
                    const int k = lane + it * 32;
                    uint4 wi = wi_p[k];
                    uint4 wh = wh_p[k];
                    float4 v0 = VI[2 * it + 0], v1 = VI[2 * it + 1];
                    float4 u0 = VH[2 * it + 0], u1 = VH[2 * it + 1];

                    float2 w0 = __half22float2(*(__half2*)&wi.x);
                    float2 w1 = __half22float2(*(__half2*)&wi.y);
                    float2 w2 = __half22float2(*(__half2*)&wi.z);
                    float2 w3 = __half22float2(*(__half2*)&wi.w);
                    a = fmaf(w0.x, v0.x, a); a = fmaf(w0.y, v0.y, a);
                    a = fmaf(w1.x, v0.z, a); a = fmaf(w1.y, v0.w, a);
                    a = fmaf(w2.x, v1.x, a); a = fmaf(w2.y, v1.y, a);
                    a = fmaf(w3.x, v1.z, a); a = fmaf(w3.y, v1.w, a);

                    float2 x0 = __half22float2(*(__half2*)&wh.x);
                    float2 x1 = __half22float2(*(__half2*)&wh.y);
                    float2 x2 = __half22float2(*(__half2*)&wh.z);
                    float2 x3 = __half22float2(*(__half2*)&wh.w);
                    a = fmaf(x0.x, u0.x, a); a = fmaf(x0.y, u0.y, a);
                    a = fmaf(x1.x, u0.z, a); a = fmaf(x1.y, u0.w, a);
                    a = fmaf(x2.x, u1.x, a); a = fmaf(x2.y, u1.y, a);
                    a = fmaf(x3.x, u1.z, a); a = fmaf(x3.y, u1.w, a);
                }
                acc[g] = a;
            }
#pragma unroll
            for (int off = 16; off > 0; off >>= 1) {
#pragma unroll
                for (int g = 0; g < 4; ++g)
                    acc[g] += __shfl_xor_sync(0xFFFFFFFFu, acc[g], off);
            }

            const float ig = sigmoidf_(acc[0] + bias[0]);
            const float fg = sigmoidf_(acc[1] + bias[1]);
            const float gg = tanhf(acc[2] + bias[2]);
            const float og = sigmoidf_(acc[3] + bias[3]);
            c = fg * c + ig * gg;
            const float h = og * tanhf(c);

            if (lane == 0) {
                if (layer) {
                    stcg_f(&g_h1[(p - 1) & 1][j], h);
                    out[(size_t)t * H + j] = h;
                    if (t == T - 1) { out[HT + H + j] = h; out[CT + H + j] = c; }
                } else {
                    stcg_f(&g_h0[p & 1][j], h);
                    if (p == T - 1) { out[HT + j] = h; out[CT + j] = c; }
                }
            }
        }

        // prefetch next embedding row into L2 (hides DRAM latency of emb)
        if (!layer && warp == 1 && p + 1 < T) {
            const char* row = (const char*)(emb + (size_t)__ldg(&idx[p + 1]) * H);
            asm volatile("prefetch.global.L2 [%0];" :: "l"(row + lane * 128));
        }

        grid_sync();   // h stores drained by barrier protocol (fence before arrive)
    }
}

extern "C" void kernel_launch(void* const* d_in, const int* in_sizes, int n_in,
                              void* d_out, int out_size) {
    const int*   idx  = (const int*)d_in[0];
    const float* emb  = (const float*)d_in[1];
    const float* W_ih = (const float*)d_in[2];
    const float* W_hh = (const float*)d_in[3];
    const float* b_ih = (const float*)d_in[4];
    const float* b_hh = (const float*)d_in[5];
    float* out = (float*)d_out;

    static int attr_set = 0;
    if (!attr_set) {
        cudaFuncSetAttribute(lstm_persistent,
                             cudaFuncAttributeMaxDynamicSharedMemorySize, SMEM_W);
        attr_set = 1;
    }
    lstm_persistent<<<NBLK, NTHR, SMEM_W>>>(idx, emb, W_ih, W_hh, b_ih, b_hh, out);
    (void)in_sizes; (void)n_in; (void)out_size;
}